// round 2
// baseline (speedup 1.0000x reference)
#include <cuda_runtime.h>
#include <math.h>

// Problem constants
#define B_   8
#define C_   256
#define N_   4096      // H*W = 64*64
#define NH_  4
#define HD_  64
#define SZ_  (B_ * C_ * N_)   // 8388608 elements per tensor
#define EPS_ 1e-5f

// ---------------------------------------------------------------------------
// Device scratch (no allocations allowed)
// ---------------------------------------------------------------------------
__device__ float g_q[SZ_];
__device__ float g_k[SZ_];
__device__ float g_v[SZ_];
__device__ float g_att[SZ_];
__device__ float g_ctx[B_ * NH_ * HD_ * HD_];   // 131072 floats
__device__ float g_mean[C_];
__device__ float g_rstd[C_];

// ---------------------------------------------------------------------------
// conv1x1 GEMM:  Y[b] = W(256x256) @ X[b](256x4096) + bias (+ residual)
// grid: (N_/128, C_/128, B_)  block: 256 threads
// Tiles: BM=128, BN=128, BK=8; per-thread 8x8.
// ---------------------------------------------------------------------------
__global__ __launch_bounds__(256, 2)
void gemm_conv(const float* __restrict__ W, const float* __restrict__ X,
               const float* __restrict__ bias, const float* __restrict__ resid,
               float* __restrict__ Y)
{
    __shared__ float As[8][128];
    __shared__ float Bs[8][128];

    const int b  = blockIdx.z;
    const float* Xb = X + (size_t)b * C_ * N_;
    float*       Yb = Y + (size_t)b * C_ * N_;
    const float* Rb = resid ? resid + (size_t)b * C_ * N_ : nullptr;

    const int m0 = blockIdx.y * 128;
    const int n0 = blockIdx.x * 128;
    const int t  = threadIdx.x;
    const int tx = t % 16;          // n-tile index
    const int ty = t / 16;          // m-tile index

    // A-tile load indices: 128 rows x 8 cols; 2 float4 per row
    const int a_r = t >> 1;
    const int a_c = (t & 1) * 4;
    // B-tile load indices: 8 rows x 128 cols
    const int b_r = t >> 5;
    const int b_c = (t & 31) * 4;

    float acc[8][8];
#pragma unroll
    for (int i = 0; i < 8; i++)
#pragma unroll
        for (int j = 0; j < 8; j++) acc[i][j] = 0.f;

    for (int kt = 0; kt < C_; kt += 8) {
        float4 av = *(const float4*)&W[(size_t)(m0 + a_r) * C_ + kt + a_c];
        As[a_c + 0][a_r] = av.x;
        As[a_c + 1][a_r] = av.y;
        As[a_c + 2][a_r] = av.z;
        As[a_c + 3][a_r] = av.w;
        *(float4*)&Bs[b_r][b_c] =
            *(const float4*)&Xb[(size_t)(kt + b_r) * N_ + n0 + b_c];
        __syncthreads();

#pragma unroll
        for (int k = 0; k < 8; k++) {
            float a[8], bb[8];
            *(float4*)&a[0]  = *(const float4*)&As[k][ty * 8];
            *(float4*)&a[4]  = *(const float4*)&As[k][ty * 8 + 4];
            *(float4*)&bb[0] = *(const float4*)&Bs[k][tx * 8];
            *(float4*)&bb[4] = *(const float4*)&Bs[k][tx * 8 + 4];
#pragma unroll
            for (int i = 0; i < 8; i++)
#pragma unroll
                for (int j = 0; j < 8; j++)
                    acc[i][j] += a[i] * bb[j];
        }
        __syncthreads();
    }

#pragma unroll
    for (int i = 0; i < 8; i++) {
        const int row = m0 + ty * 8 + i;
        const float bv = bias[row];
        float* yp = &Yb[(size_t)row * N_ + n0 + tx * 8];
        const float* rp = Rb ? &Rb[(size_t)row * N_ + n0 + tx * 8] : nullptr;
#pragma unroll
        for (int jj = 0; jj < 8; jj += 4) {
            float4 o;
            o.x = acc[i][jj + 0] + bv;
            o.y = acc[i][jj + 1] + bv;
            o.z = acc[i][jj + 2] + bv;
            o.w = acc[i][jj + 3] + bv;
            if (rp) {
                float4 r = *(const float4*)&rp[jj];
                o.x += r.x; o.y += r.y; o.z += r.z; o.w += r.w;
            }
            *(float4*)&yp[jj] = o;
        }
    }
}

// ---------------------------------------------------------------------------
// Row softmax over N_=4096, in place. One block (256 thr) per row; row in regs.
// grid: B_*C_ = 2048
// ---------------------------------------------------------------------------
__global__ __launch_bounds__(256)
void softmax_rows(float* __restrict__ X)
{
    const int row = blockIdx.x;
    float* p = X + (size_t)row * N_;
    const int t = threadIdx.x;

    float v[16];
    float mx = -INFINITY;
#pragma unroll
    for (int j = 0; j < 16; j++) {
        v[j] = p[t + 256 * j];
        mx = fmaxf(mx, v[j]);
    }

    __shared__ float red[8];
#pragma unroll
    for (int o = 16; o; o >>= 1) mx = fmaxf(mx, __shfl_xor_sync(0xFFFFFFFFu, mx, o));
    if ((t & 31) == 0) red[t >> 5] = mx;
    __syncthreads();
    mx = red[0];
#pragma unroll
    for (int w = 1; w < 8; w++) mx = fmaxf(mx, red[w]);

    float s = 0.f;
#pragma unroll
    for (int j = 0; j < 16; j++) {
        v[j] = expf(v[j] - mx);
        s += v[j];
    }
#pragma unroll
    for (int o = 16; o; o >>= 1) s += __shfl_xor_sync(0xFFFFFFFFu, s, o);
    __syncthreads();                 // protect red[] reuse
    if ((t & 31) == 0) red[t >> 5] = s;
    __syncthreads();
    s = 0.f;
#pragma unroll
    for (int w = 0; w < 8; w++) s += red[w];

    const float inv = 1.0f / s;
#pragma unroll
    for (int j = 0; j < 16; j++) p[t + 256 * j] = v[j] * inv;
}

// ---------------------------------------------------------------------------
// zero a float buffer
// ---------------------------------------------------------------------------
__global__ void zero_kernel(float* __restrict__ p, int n)
{
    int i = blockIdx.x * blockDim.x + threadIdx.x;
    if (i < n) p[i] = 0.f;
}

// ---------------------------------------------------------------------------
// context[bh][d][e] += sum_n k[d,n] * v[e,n]    (split-K over n, atomics)
// grid: (B_*NH_, CTX_SPLIT)  block: 256
// ---------------------------------------------------------------------------
#define CTX_SPLIT 8
__global__ __launch_bounds__(256)
void ctx_kernel(const float* __restrict__ K, const float* __restrict__ V,
                float* __restrict__ ctx)
{
    const int bh = blockIdx.x;
    const int b = bh / NH_, h = bh % NH_;
    const float* Kb = K + ((size_t)b * C_ + h * HD_) * N_;
    const float* Vb = V + ((size_t)b * C_ + h * HD_) * N_;
    float* cp = ctx + (size_t)bh * HD_ * HD_;

    const int nbeg = blockIdx.y * (N_ / CTX_SPLIT);
    __shared__ float Ks[16][64];
    __shared__ float Vs[16][64];

    const int t = threadIdx.x;
    const int tx = t % 16;          // e group (4 wide)
    const int ty = t / 16;          // d group (4 wide)
    const int lr = t / 4;           // load row 0..63
    const int lc = (t % 4) * 4;     // load col offset 0..12

    float acc[4][4];
#pragma unroll
    for (int i = 0; i < 4; i++)
#pragma unroll
        for (int j = 0; j < 4; j++) acc[i][j] = 0.f;

    for (int n0 = nbeg; n0 < nbeg + N_ / CTX_SPLIT; n0 += 16) {
        float4 kv = *(const float4*)&Kb[(size_t)lr * N_ + n0 + lc];
        float4 vv = *(const float4*)&Vb[(size_t)lr * N_ + n0 + lc];
        Ks[lc + 0][lr] = kv.x; Ks[lc + 1][lr] = kv.y;
        Ks[lc + 2][lr] = kv.z; Ks[lc + 3][lr] = kv.w;
        Vs[lc + 0][lr] = vv.x; Vs[lc + 1][lr] = vv.y;
        Vs[lc + 2][lr] = vv.z; Vs[lc + 3][lr] = vv.w;
        __syncthreads();

#pragma unroll
        for (int nn = 0; nn < 16; nn++) {
            float kd[4], ve[4];
            *(float4*)kd = *(const float4*)&Ks[nn][ty * 4];
            *(float4*)ve = *(const float4*)&Vs[nn][tx * 4];
#pragma unroll
            for (int i = 0; i < 4; i++)
#pragma unroll
                for (int j = 0; j < 4; j++)
                    acc[i][j] += kd[i] * ve[j];
        }
        __syncthreads();
    }

#pragma unroll
    for (int i = 0; i < 4; i++)
#pragma unroll
        for (int j = 0; j < 4; j++)
            atomicAdd(&cp[(size_t)(ty * 4 + i) * HD_ + tx * 4 + j], acc[i][j]);
}

// ---------------------------------------------------------------------------
// out[bh][e][n] = sum_d ctx[d][e] * q[d][n]
// grid: (N_/64, B_*NH_)  block: 256.   ctx tile + q tile cached in smem.
// ---------------------------------------------------------------------------
__global__ __launch_bounds__(256)
void attnout_kernel(const float* __restrict__ Q, const float* __restrict__ ctx,
                    float* __restrict__ O)
{
    const int bh = blockIdx.y;
    const int b = bh / NH_, h = bh % NH_;
    const float* Qb = Q + ((size_t)b * C_ + h * HD_) * N_;
    float*       Ob = O + ((size_t)b * C_ + h * HD_) * N_;
    const float* cp = ctx + (size_t)bh * HD_ * HD_;
    const int n0 = blockIdx.x * 64;

    __shared__ float Cs[64][64];    // ctx[d][e]
    __shared__ float Qs[64][64];    // q[d][n-n0]

    const int t = threadIdx.x;

    // load ctx (4096 floats = 1024 float4)
    for (int i = t; i < 1024; i += 256)
        ((float4*)&Cs[0][0])[i] = ((const float4*)cp)[i];

    // load Q tile
    const int qr = t / 16;          // 0..15
    const int qc = (t % 16) * 4;    // 0..60
    for (int d = qr; d < 64; d += 16)
        *(float4*)&Qs[d][qc] = *(const float4*)&Qb[(size_t)d * N_ + n0 + qc];
    __syncthreads();

    const int tx = t % 16;          // n group (4 wide)
    const int ty = t / 16;          // e group (4 wide)

    float acc[4][4];
#pragma unroll
    for (int i = 0; i < 4; i++)
#pragma unroll
        for (int j = 0; j < 4; j++) acc[i][j] = 0.f;

#pragma unroll 4
    for (int d = 0; d < 64; d++) {
        float qv[4], cv[4];
        *(float4*)qv = *(const float4*)&Qs[d][tx * 4];
        *(float4*)cv = *(const float4*)&Cs[d][ty * 4];
#pragma unroll
        for (int i = 0; i < 4; i++)
#pragma unroll
            for (int j = 0; j < 4; j++)
                acc[i][j] += cv[i] * qv[j];
    }

#pragma unroll
    for (int i = 0; i < 4; i++) {
        float4 o = make_float4(acc[i][0], acc[i][1], acc[i][2], acc[i][3]);
        *(float4*)&Ob[(size_t)(ty * 4 + i) * N_ + n0 + tx * 4] = o;
    }
}

// ---------------------------------------------------------------------------
// BN statistics: one block per channel; mean + rstd over B_*N_ values
// ---------------------------------------------------------------------------
__global__ __launch_bounds__(256)
void bn_stats(const float* __restrict__ X, float* __restrict__ mean,
              float* __restrict__ rstd)
{
    const int c = blockIdx.x;
    const int t = threadIdx.x;
    float s = 0.f, ss = 0.f;
    for (int b = 0; b < B_; b++) {
        const float* p = X + ((size_t)b * C_ + c) * N_;
        for (int i = t * 4; i < N_; i += 1024) {
            float4 v = *(const float4*)&p[i];
            s  += v.x + v.y + v.z + v.w;
            ss += v.x * v.x + v.y * v.y + v.z * v.z + v.w * v.w;
        }
    }
    __shared__ float rs[8], rss[8];
#pragma unroll
    for (int o = 16; o; o >>= 1) {
        s  += __shfl_xor_sync(0xFFFFFFFFu, s, o);
        ss += __shfl_xor_sync(0xFFFFFFFFu, ss, o);
    }
    if ((t & 31) == 0) { rs[t >> 5] = s; rss[t >> 5] = ss; }
    __syncthreads();
    if (t == 0) {
        float S = 0.f, SS = 0.f;
        for (int w = 0; w < 8; w++) { S += rs[w]; SS += rss[w]; }
        const float inv_n = 1.0f / (float)(B_ * N_);
        const float m = S * inv_n;
        const float var = SS * inv_n - m * m;
        mean[c] = m;
        rstd[c] = rsqrtf(var + EPS_);
    }
}

// ---------------------------------------------------------------------------
// BN apply, in place, vectorized
// ---------------------------------------------------------------------------
__global__ __launch_bounds__(256)
void bn_apply(float* __restrict__ X, const float* __restrict__ mean,
              const float* __restrict__ rstd, const float* __restrict__ gamma,
              const float* __restrict__ beta)
{
    const size_t i = ((size_t)blockIdx.x * blockDim.x + threadIdx.x) * 4;
    if (i >= (size_t)SZ_) return;
    const int c = (int)((i / N_) % C_);
    const float m = mean[c], r = rstd[c], g = gamma[c], be = beta[c];
    float4 v = *(float4*)&X[i];
    v.x = (v.x - m) * r * g + be;
    v.y = (v.y - m) * r * g + be;
    v.z = (v.z - m) * r * g + be;
    v.w = (v.w - m) * r * g + be;
    *(float4*)&X[i] = v;
}

// ---------------------------------------------------------------------------
// Host orchestration
// ---------------------------------------------------------------------------
static void run_branch(const float* x, const float* y,
                       const float* wq, const float* bq,
                       const float* wk, const float* bk,
                       const float* wv, const float* bv,
                       const float* wp, const float* bp,
                       float* out,
                       float* pq, float* pk, float* pv, float* patt, float* pctx)
{
    dim3 ggrid(N_ / 128, C_ / 128, B_);
    gemm_conv<<<ggrid, 256>>>(wq, x, bq, nullptr, pq);
    gemm_conv<<<ggrid, 256>>>(wk, y, bk, nullptr, pk);
    gemm_conv<<<ggrid, 256>>>(wv, y, bv, nullptr, pv);

    softmax_rows<<<B_ * C_, 256>>>(pq);
    softmax_rows<<<B_ * C_, 256>>>(pk);

    zero_kernel<<<(B_ * NH_ * HD_ * HD_ + 255) / 256, 256>>>(pctx, B_ * NH_ * HD_ * HD_);
    ctx_kernel<<<dim3(B_ * NH_, CTX_SPLIT), 256>>>(pk, pv, pctx);
    attnout_kernel<<<dim3(N_ / 64, B_ * NH_), 256>>>(pq, pctx, patt);

    gemm_conv<<<ggrid, 256>>>(wp, patt, bp, /*resid=*/x, out);
}

extern "C" void kernel_launch(void* const* d_in, const int* in_sizes, int n_in,
                              void* d_out, int out_size)
{
    const float* rgb_low  = (const float*)d_in[0];
    const float* rgb_high = (const float*)d_in[1];
    const float* dsm_low  = (const float*)d_in[2];
    const float* dsm_high = (const float*)d_in[3];
    const float* w_q1 = (const float*)d_in[4];   const float* b_q1 = (const float*)d_in[5];
    const float* w_k1 = (const float*)d_in[6];   const float* b_k1 = (const float*)d_in[7];
    const float* w_v1 = (const float*)d_in[8];   const float* b_v1 = (const float*)d_in[9];
    const float* w_q2 = (const float*)d_in[10];  const float* b_q2 = (const float*)d_in[11];
    const float* w_k2 = (const float*)d_in[12];  const float* b_k2 = (const float*)d_in[13];
    const float* w_v2 = (const float*)d_in[14];  const float* b_v2 = (const float*)d_in[15];
    const float* w_p1 = (const float*)d_in[16];  const float* b_p1 = (const float*)d_in[17];
    const float* w_p2 = (const float*)d_in[18];  const float* b_p2 = (const float*)d_in[19];
    const float* gamma = (const float*)d_in[20];
    const float* beta  = (const float*)d_in[21];

    float* out = (float*)d_out;
    float* o_rl = out;
    float* o_rh = out + (size_t)SZ_;
    float* o_dl = out + (size_t)2 * SZ_;
    float* o_dh = out + (size_t)3 * SZ_;

    float *pq, *pk, *pv, *patt, *pctx, *pmean, *prstd;
    cudaGetSymbolAddress((void**)&pq,    g_q);
    cudaGetSymbolAddress((void**)&pk,    g_k);
    cudaGetSymbolAddress((void**)&pv,    g_v);
    cudaGetSymbolAddress((void**)&patt,  g_att);
    cudaGetSymbolAddress((void**)&pctx,  g_ctx);
    cudaGetSymbolAddress((void**)&pmean, g_mean);
    cudaGetSymbolAddress((void**)&prstd, g_rstd);

    // Branch 1: q from rgb_low; k,v from dsm_high; residual into rgb_low
    run_branch(rgb_low, dsm_high, w_q1, b_q1, w_k1, b_k1, w_v1, b_v1,
               w_p1, b_p1, o_rl, pq, pk, pv, patt, pctx);

    // Branch 2: q from rgb_high; k,v from dsm_low; residual into rgb_high
    run_branch(rgb_high, dsm_low, w_q2, b_q2, w_k2, b_k2, w_v2, b_v2,
               w_p2, b_p2, o_rh, pq, pk, pv, patt, pctx);

    // BatchNorm (train mode, batch stats) on both rgb outputs, in place
    bn_stats<<<C_, 256>>>(o_rl, pmean, prstd);
    bn_apply<<<SZ_ / 4 / 256, 256>>>(o_rl, pmean, prstd, gamma, beta);
    bn_stats<<<C_, 256>>>(o_rh, pmean, prstd);
    bn_apply<<<SZ_ / 4 / 256, 256>>>(o_rh, pmean, prstd, gamma, beta);

    // dsm tensors pass through unchanged
    cudaMemcpyAsync(o_dl, dsm_low,  (size_t)SZ_ * sizeof(float),
                    cudaMemcpyDeviceToDevice);
    cudaMemcpyAsync(o_dh, dsm_high, (size_t)SZ_ * sizeof(float),
                    cudaMemcpyDeviceToDevice);
}

// round 4
// speedup vs baseline: 1.9760x; 1.9760x over previous
#include <cuda_runtime.h>
#include <math.h>
#include <stdint.h>

// Problem constants
#define B_   8
#define C_   256
#define N_   4096      // H*W = 64*64
#define NH_  4
#define HD_  64
#define SZ_  (B_ * C_ * N_)   // 8388608 elements per tensor
#define EPS_ 1e-5f

// ---------------------------------------------------------------------------
// Device scratch (no allocations allowed)
// ---------------------------------------------------------------------------
__device__ float g_q[SZ_];
__device__ float g_k[SZ_];
__device__ float g_v[SZ_];
__device__ float g_att[SZ_];
__device__ float g_ctx[B_ * NH_ * HD_ * HD_];   // 131072 floats
__device__ float g_mean[C_];
__device__ float g_rstd[C_];

// ---------------------------------------------------------------------------
// fp32 -> tf32 (round to nearest)
// ---------------------------------------------------------------------------
__device__ __forceinline__ uint32_t f2tf32(float x)
{
    uint32_t r;
    asm("cvt.rna.tf32.f32 %0, %1;" : "=r"(r) : "f"(x));
    return r;
}

__device__ __forceinline__ void mma_tf32(float* c, const uint32_t* a, const uint32_t* b)
{
    asm volatile(
        "mma.sync.aligned.m16n8k8.row.col.f32.tf32.tf32.f32 "
        "{%0,%1,%2,%3}, {%4,%5,%6,%7}, {%8,%9}, {%0,%1,%2,%3};\n"
        : "+f"(c[0]), "+f"(c[1]), "+f"(c[2]), "+f"(c[3])
        : "r"(a[0]), "r"(a[1]), "r"(a[2]), "r"(a[3]),
          "r"(b[0]), "r"(b[1]));
}

// ---------------------------------------------------------------------------
// conv1x1 GEMM (tf32 tensor cores):
//   Y[b] = W(256x256) @ X[b](256x4096) + bias (+ residual)
// grid: (N_/128, C_/128, B_)  block: 256 threads (8 warps, 2x4 warp tiles)
// Block tile 128x128x16; warp tile 64x32; mma m16n8k8.
// Smem: A [m][K=16 pad->20] (bank-conflict-free for frag loads),
//       B [k][N=128 pad->136].
// ---------------------------------------------------------------------------
#define BKg 16
#define A_STRIDE 20
#define B_STRIDE 136

__global__ __launch_bounds__(256, 2)
void gemm_conv_tf32(const float* __restrict__ W, const float* __restrict__ X,
                    const float* __restrict__ bias, const float* __restrict__ resid,
                    float* __restrict__ Y)
{
    __shared__ uint32_t As[128 * A_STRIDE];   // [m][20]
    __shared__ uint32_t Bs[BKg * B_STRIDE];   // [k][136]

    const int b  = blockIdx.z;
    const float* Xb = X + (size_t)b * C_ * N_;
    float*       Yb = Y + (size_t)b * C_ * N_;
    const float* Rb = resid ? resid + (size_t)b * C_ * N_ : nullptr;

    const int m0 = blockIdx.y * 128;
    const int n0 = blockIdx.x * 128;
    const int t  = threadIdx.x;
    const int wid  = t >> 5;
    const int lane = t & 31;
    const int g  = lane >> 2;   // group id 0..7
    const int t4 = lane & 3;    // thread in group 0..3
    const int warp_m = (wid & 1) * 64;   // 0 or 64
    const int warp_n = (wid >> 1) * 32;  // 0,32,64,96

    // Global-load tiling (float4 granularity):
    // A tile: 128 rows x 16 cols = 512 float4 -> ids t, t+256; row=id/4, c4=id%4
    // B tile:  16 rows x 128 cols = 512 float4 -> ids t, t+256; row=id/32, c4=id%32
    const int aR0 = t >> 2,          aC0 = (t & 3) * 4;
    const int aR1 = (t + 256) >> 2,  aC1 = ((t + 256) & 3) * 4;
    const int bR0 = t >> 5,          bC0 = (t & 31) * 4;
    const int bR1 = (t + 256) >> 5,  bC1 = ((t + 256) & 31) * 4;

    float4 rA0, rA1, rB0, rB1;

#define LDG_TILES(kt)                                                          \
    do {                                                                       \
        rA0 = *(const float4*)&W[(size_t)(m0 + aR0) * C_ + (kt) + aC0];        \
        rA1 = *(const float4*)&W[(size_t)(m0 + aR1) * C_ + (kt) + aC1];        \
        rB0 = *(const float4*)&Xb[(size_t)((kt) + bR0) * N_ + n0 + bC0];       \
        rB1 = *(const float4*)&Xb[(size_t)((kt) + bR1) * N_ + n0 + bC1];       \
    } while (0)

#define STS_TILES()                                                            \
    do {                                                                       \
        uint4 u;                                                               \
        u.x = f2tf32(rA0.x); u.y = f2tf32(rA0.y);                              \
        u.z = f2tf32(rA0.z); u.w = f2tf32(rA0.w);                              \
        *(uint4*)&As[aR0 * A_STRIDE + aC0] = u;                                \
        u.x = f2tf32(rA1.x); u.y = f2tf32(rA1.y);                              \
        u.z = f2tf32(rA1.z); u.w = f2tf32(rA1.w);                              \
        *(uint4*)&As[aR1 * A_STRIDE + aC1] = u;                                \
        u.x = f2tf32(rB0.x); u.y = f2tf32(rB0.y);                              \
        u.z = f2tf32(rB0.z); u.w = f2tf32(rB0.w);                              \
        *(uint4*)&Bs[bR0 * B_STRIDE + bC0] = u;                                \
        u.x = f2tf32(rB1.x); u.y = f2tf32(rB1.y);                              \
        u.z = f2tf32(rB1.z); u.w = f2tf32(rB1.w);                              \
        *(uint4*)&Bs[bR1 * B_STRIDE + bC1] = u;                                \
    } while (0)

    float acc[4][4][4];
#pragma unroll
    for (int mt = 0; mt < 4; mt++)
#pragma unroll
        for (int nt = 0; nt < 4; nt++)
#pragma unroll
            for (int i = 0; i < 4; i++) acc[mt][nt][i] = 0.f;

    LDG_TILES(0);
    STS_TILES();
    __syncthreads();

    for (int kt = 0; kt < C_; kt += BKg) {
        const bool has_next = (kt + BKg) < C_;
        if (has_next) LDG_TILES(kt + BKg);

#pragma unroll
        for (int ks = 0; ks < 2; ks++) {
            const int kk = ks * 8;
            uint32_t afr[4][4], bfr[4][2];
#pragma unroll
            for (int mt = 0; mt < 4; mt++) {
                const int mr = warp_m + mt * 16 + g;
                afr[mt][0] = As[(mr)     * A_STRIDE + kk + t4];
                afr[mt][1] = As[(mr + 8) * A_STRIDE + kk + t4];
                afr[mt][2] = As[(mr)     * A_STRIDE + kk + t4 + 4];
                afr[mt][3] = As[(mr + 8) * A_STRIDE + kk + t4 + 4];
            }
#pragma unroll
            for (int nt = 0; nt < 4; nt++) {
                const int nc = warp_n + nt * 8 + g;
                bfr[nt][0] = Bs[(kk + t4)     * B_STRIDE + nc];
                bfr[nt][1] = Bs[(kk + t4 + 4) * B_STRIDE + nc];
            }
#pragma unroll
            for (int mt = 0; mt < 4; mt++)
#pragma unroll
                for (int nt = 0; nt < 4; nt++)
                    mma_tf32(acc[mt][nt], afr[mt], bfr[nt]);
        }

        if (has_next) {
            __syncthreads();
            STS_TILES();
            __syncthreads();
        }
    }

    // Epilogue: bias + optional residual; each mma tile writes float2 pairs.
#pragma unroll
    for (int mt = 0; mt < 4; mt++) {
        const int r0 = m0 + warp_m + mt * 16 + g;
        const int r1 = r0 + 8;
        const float bv0 = bias[r0];
        const float bv1 = bias[r1];
#pragma unroll
        for (int nt = 0; nt < 4; nt++) {
            const int cc = n0 + warp_n + nt * 8 + t4 * 2;
            float2 o0, o1;
            o0.x = acc[mt][nt][0] + bv0;
            o0.y = acc[mt][nt][1] + bv0;
            o1.x = acc[mt][nt][2] + bv1;
            o1.y = acc[mt][nt][3] + bv1;
            if (Rb) {
                float2 x0 = *(const float2*)&Rb[(size_t)r0 * N_ + cc];
                float2 x1 = *(const float2*)&Rb[(size_t)r1 * N_ + cc];
                o0.x += x0.x; o0.y += x0.y;
                o1.x += x1.x; o1.y += x1.y;
            }
            *(float2*)&Yb[(size_t)r0 * N_ + cc] = o0;
            *(float2*)&Yb[(size_t)r1 * N_ + cc] = o1;
        }
    }
#undef LDG_TILES
#undef STS_TILES
}

// ---------------------------------------------------------------------------
// Row softmax over N_=4096, in place. One block (256 thr) per row; row in regs.
// grid: B_*C_ = 2048
// ---------------------------------------------------------------------------
__global__ __launch_bounds__(256)
void softmax_rows(float* __restrict__ X)
{
    const int row = blockIdx.x;
    float* p = X + (size_t)row * N_;
    const int t = threadIdx.x;

    float v[16];
    float mx = -INFINITY;
#pragma unroll
    for (int j = 0; j < 16; j++) {
        v[j] = p[t + 256 * j];
        mx = fmaxf(mx, v[j]);
    }

    __shared__ float red[8];
#pragma unroll
    for (int o = 16; o; o >>= 1) mx = fmaxf(mx, __shfl_xor_sync(0xFFFFFFFFu, mx, o));
    if ((t & 31) == 0) red[t >> 5] = mx;
    __syncthreads();
    mx = red[0];
#pragma unroll
    for (int w = 1; w < 8; w++) mx = fmaxf(mx, red[w]);

    float s = 0.f;
#pragma unroll
    for (int j = 0; j < 16; j++) {
        v[j] = expf(v[j] - mx);
        s += v[j];
    }
#pragma unroll
    for (int o = 16; o; o >>= 1) s += __shfl_xor_sync(0xFFFFFFFFu, s, o);
    __syncthreads();                 // protect red[] reuse
    if ((t & 31) == 0) red[t >> 5] = s;
    __syncthreads();
    s = 0.f;
#pragma unroll
    for (int w = 0; w < 8; w++) s += red[w];

    const float inv = 1.0f / s;
#pragma unroll
    for (int j = 0; j < 16; j++) p[t + 256 * j] = v[j] * inv;
}

// ---------------------------------------------------------------------------
// zero a float buffer
// ---------------------------------------------------------------------------
__global__ void zero_kernel(float* __restrict__ p, int n)
{
    int i = blockIdx.x * blockDim.x + threadIdx.x;
    if (i < n) p[i] = 0.f;
}

// ---------------------------------------------------------------------------
// context[bh][d][e] += sum_n k[d,n] * v[e,n]    (split-K over n, atomics)
// grid: (B_*NH_, CTX_SPLIT)  block: 256
// ---------------------------------------------------------------------------
#define CTX_SPLIT 8
__global__ __launch_bounds__(256)
void ctx_kernel(const float* __restrict__ K, const float* __restrict__ V,
                float* __restrict__ ctx)
{
    const int bh = blockIdx.x;
    const int b = bh / NH_, h = bh % NH_;
    const float* Kb = K + ((size_t)b * C_ + h * HD_) * N_;
    const float* Vb = V + ((size_t)b * C_ + h * HD_) * N_;
    float* cp = ctx + (size_t)bh * HD_ * HD_;

    const int nbeg = blockIdx.y * (N_ / CTX_SPLIT);
    __shared__ float Ks[16][64];
    __shared__ float Vs[16][64];

    const int t = threadIdx.x;
    const int tx = t % 16;          // e group (4 wide)
    const int ty = t / 16;          // d group (4 wide)
    const int lr = t / 4;           // load row 0..63
    const int lc = (t % 4) * 4;     // load col offset 0..12

    float acc[4][4];
#pragma unroll
    for (int i = 0; i < 4; i++)
#pragma unroll
        for (int j = 0; j < 4; j++) acc[i][j] = 0.f;

    for (int n0 = nbeg; n0 < nbeg + N_ / CTX_SPLIT; n0 += 16) {
        float4 kv = *(const float4*)&Kb[(size_t)lr * N_ + n0 + lc];
        float4 vv = *(const float4*)&Vb[(size_t)lr * N_ + n0 + lc];
        Ks[lc + 0][lr] = kv.x; Ks[lc + 1][lr] = kv.y;
        Ks[lc + 2][lr] = kv.z; Ks[lc + 3][lr] = kv.w;
        Vs[lc + 0][lr] = vv.x; Vs[lc + 1][lr] = vv.y;
        Vs[lc + 2][lr] = vv.z; Vs[lc + 3][lr] = vv.w;
        __syncthreads();

#pragma unroll
        for (int nn = 0; nn < 16; nn++) {
            float kd[4], ve[4];
            *(float4*)kd = *(const float4*)&Ks[nn][ty * 4];
            *(float4*)ve = *(const float4*)&Vs[nn][tx * 4];
#pragma unroll
            for (int i = 0; i < 4; i++)
#pragma unroll
                for (int j = 0; j < 4; j++)
                    acc[i][j] += kd[i] * ve[j];
        }
        __syncthreads();
    }

#pragma unroll
    for (int i = 0; i < 4; i++)
#pragma unroll
        for (int j = 0; j < 4; j++)
            atomicAdd(&cp[(size_t)(ty * 4 + i) * HD_ + tx * 4 + j], acc[i][j]);
}

// ---------------------------------------------------------------------------
// out[bh][e][n] = sum_d ctx[d][e] * q[d][n]
// grid: (N_/64, B_*NH_)  block: 256.   ctx tile + q tile cached in smem.
// ---------------------------------------------------------------------------
__global__ __launch_bounds__(256)
void attnout_kernel(const float* __restrict__ Q, const float* __restrict__ ctx,
                    float* __restrict__ O)
{
    const int bh = blockIdx.y;
    const int b = bh / NH_, h = bh % NH_;
    const float* Qb = Q + ((size_t)b * C_ + h * HD_) * N_;
    float*       Ob = O + ((size_t)b * C_ + h * HD_) * N_;
    const float* cp = ctx + (size_t)bh * HD_ * HD_;
    const int n0 = blockIdx.x * 64;

    __shared__ float Cs[64][64];    // ctx[d][e]
    __shared__ float Qs[64][64];    // q[d][n-n0]

    const int t = threadIdx.x;

    // load ctx (4096 floats = 1024 float4)
    for (int i = t; i < 1024; i += 256)
        ((float4*)&Cs[0][0])[i] = ((const float4*)cp)[i];

    // load Q tile
    const int qr = t / 16;          // 0..15
    const int qc = (t % 16) * 4;    // 0..60
    for (int d = qr; d < 64; d += 16)
        *(float4*)&Qs[d][qc] = *(const float4*)&Qb[(size_t)d * N_ + n0 + qc];
    __syncthreads();

    const int tx = t % 16;          // n group (4 wide)
    const int ty = t / 16;          // e group (4 wide)

    float acc[4][4];
#pragma unroll
    for (int i = 0; i < 4; i++)
#pragma unroll
        for (int j = 0; j < 4; j++) acc[i][j] = 0.f;

#pragma unroll 4
    for (int d = 0; d < 64; d++) {
        float qv[4], cv[4];
        *(float4*)qv = *(const float4*)&Qs[d][tx * 4];
        *(float4*)cv = *(const float4*)&Cs[d][ty * 4];
#pragma unroll
        for (int i = 0; i < 4; i++)
#pragma unroll
            for (int j = 0; j < 4; j++)
                acc[i][j] += cv[i] * qv[j];
    }

#pragma unroll
    for (int i = 0; i < 4; i++) {
        float4 o = make_float4(acc[i][0], acc[i][1], acc[i][2], acc[i][3]);
        *(float4*)&Ob[(size_t)(ty * 4 + i) * N_ + n0 + tx * 4] = o;
    }
}

// ---------------------------------------------------------------------------
// BN statistics: one block per channel; mean + rstd over B_*N_ values
// ---------------------------------------------------------------------------
__global__ __launch_bounds__(256)
void bn_stats(const float* __restrict__ X, float* __restrict__ mean,
              float* __restrict__ rstd)
{
    const int c = blockIdx.x;
    const int t = threadIdx.x;
    float s = 0.f, ss = 0.f;
    for (int b = 0; b < B_; b++) {
        const float* p = X + ((size_t)b * C_ + c) * N_;
        for (int i = t * 4; i < N_; i += 1024) {
            float4 v = *(const float4*)&p[i];
            s  += v.x + v.y + v.z + v.w;
            ss += v.x * v.x + v.y * v.y + v.z * v.z + v.w * v.w;
        }
    }
    __shared__ float rs[8], rss[8];
#pragma unroll
    for (int o = 16; o; o >>= 1) {
        s  += __shfl_xor_sync(0xFFFFFFFFu, s, o);
        ss += __shfl_xor_sync(0xFFFFFFFFu, ss, o);
    }
    if ((t & 31) == 0) { rs[t >> 5] = s; rss[t >> 5] = ss; }
    __syncthreads();
    if (t == 0) {
        float S = 0.f, SS = 0.f;
        for (int w = 0; w < 8; w++) { S += rs[w]; SS += rss[w]; }
        const float inv_n = 1.0f / (float)(B_ * N_);
        const float m = S * inv_n;
        const float var = SS * inv_n - m * m;
        mean[c] = m;
        rstd[c] = rsqrtf(var + EPS_);
    }
}

// ---------------------------------------------------------------------------
// BN apply, in place, vectorized
// ---------------------------------------------------------------------------
__global__ __launch_bounds__(256)
void bn_apply(float* __restrict__ X, const float* __restrict__ mean,
              const float* __restrict__ rstd, const float* __restrict__ gamma,
              const float* __restrict__ beta)
{
    const size_t i = ((size_t)blockIdx.x * blockDim.x + threadIdx.x) * 4;
    if (i >= (size_t)SZ_) return;
    const int c = (int)((i / N_) % C_);
    const float m = mean[c], r = rstd[c], g = gamma[c], be = beta[c];
    float4 v = *(float4*)&X[i];
    v.x = (v.x - m) * r * g + be;
    v.y = (v.y - m) * r * g + be;
    v.z = (v.z - m) * r * g + be;
    v.w = (v.w - m) * r * g + be;
    *(float4*)&X[i] = v;
}

// ---------------------------------------------------------------------------
// Host orchestration
// ---------------------------------------------------------------------------
static void run_branch(const float* x, const float* y,
                       const float* wq, const float* bq,
                       const float* wk, const float* bk,
                       const float* wv, const float* bv,
                       const float* wp, const float* bp,
                       float* out,
                       float* pq, float* pk, float* pv, float* patt, float* pctx)
{
    dim3 ggrid(N_ / 128, C_ / 128, B_);
    gemm_conv_tf32<<<ggrid, 256>>>(wq, x, bq, nullptr, pq);
    gemm_conv_tf32<<<ggrid, 256>>>(wk, y, bk, nullptr, pk);
    gemm_conv_tf32<<<ggrid, 256>>>(wv, y, bv, nullptr, pv);

    softmax_rows<<<B_ * C_, 256>>>(pq);
    softmax_rows<<<B_ * C_, 256>>>(pk);

    zero_kernel<<<(B_ * NH_ * HD_ * HD_ + 255) / 256, 256>>>(pctx, B_ * NH_ * HD_ * HD_);
    ctx_kernel<<<dim3(B_ * NH_, CTX_SPLIT), 256>>>(pk, pv, pctx);
    attnout_kernel<<<dim3(N_ / 64, B_ * NH_), 256>>>(pq, pctx, patt);

    gemm_conv_tf32<<<ggrid, 256>>>(wp, patt, bp, /*resid=*/x, out);
}

extern "C" void kernel_launch(void* const* d_in, const int* in_sizes, int n_in,
                              void* d_out, int out_size)
{
    const float* rgb_low  = (const float*)d_in[0];
    const float* rgb_high = (const float*)d_in[1];
    const float* dsm_low  = (const float*)d_in[2];
    const float* dsm_high = (const float*)d_in[3];
    const float* w_q1 = (const float*)d_in[4];   const float* b_q1 = (const float*)d_in[5];
    const float* w_k1 = (const float*)d_in[6];   const float* b_k1 = (const float*)d_in[7];
    const float* w_v1 = (const float*)d_in[8];   const float* b_v1 = (const float*)d_in[9];
    const float* w_q2 = (const float*)d_in[10];  const float* b_q2 = (const float*)d_in[11];
    const float* w_k2 = (const float*)d_in[12];  const float* b_k2 = (const float*)d_in[13];
    const float* w_v2 = (const float*)d_in[14];  const float* b_v2 = (const float*)d_in[15];
    const float* w_p1 = (const float*)d_in[16];  const float* b_p1 = (const float*)d_in[17];
    const float* w_p2 = (const float*)d_in[18];  const float* b_p2 = (const float*)d_in[19];
    const float* gamma = (const float*)d_in[20];
    const float* beta  = (const float*)d_in[21];

    float* out = (float*)d_out;
    float* o_rl = out;
    float* o_rh = out + (size_t)SZ_;
    float* o_dl = out + (size_t)2 * SZ_;
    float* o_dh = out + (size_t)3 * SZ_;

    float *pq, *pk, *pv, *patt, *pctx, *pmean, *prstd;
    cudaGetSymbolAddress((void**)&pq,    g_q);
    cudaGetSymbolAddress((void**)&pk,    g_k);
    cudaGetSymbolAddress((void**)&pv,    g_v);
    cudaGetSymbolAddress((void**)&patt,  g_att);
    cudaGetSymbolAddress((void**)&pctx,  g_ctx);
    cudaGetSymbolAddress((void**)&pmean, g_mean);
    cudaGetSymbolAddress((void**)&prstd, g_rstd);

    // Branch 1: q from rgb_low; k,v from dsm_high; residual into rgb_low
    run_branch(rgb_low, dsm_high, w_q1, b_q1, w_k1, b_k1, w_v1, b_v1,
               w_p1, b_p1, o_rl, pq, pk, pv, patt, pctx);

    // Branch 2: q from rgb_high; k,v from dsm_low; residual into rgb_high
    run_branch(rgb_high, dsm_low, w_q2, b_q2, w_k2, b_k2, w_v2, b_v2,
               w_p2, b_p2, o_rh, pq, pk, pv, patt, pctx);

    // BatchNorm (train mode, batch stats) on both rgb outputs, in place
    bn_stats<<<C_, 256>>>(o_rl, pmean, prstd);
    bn_apply<<<SZ_ / 4 / 256, 256>>>(o_rl, pmean, prstd, gamma, beta);
    bn_stats<<<C_, 256>>>(o_rh, pmean, prstd);
    bn_apply<<<SZ_ / 4 / 256, 256>>>(o_rh, pmean, prstd, gamma, beta);

    // dsm tensors pass through unchanged
    cudaMemcpyAsync(o_dl, dsm_low,  (size_t)SZ_ * sizeof(float),
                    cudaMemcpyDeviceToDevice);
    cudaMemcpyAsync(o_dh, dsm_high, (size_t)SZ_ * sizeof(float),
                    cudaMemcpyDeviceToDevice);
}